// round 8
// baseline (speedup 1.0000x reference)
#include <cuda_runtime.h>

#define N_TOK 16384
#define NHEAD 4
#define NCODE 1024
#define DH    256
#define TM    128
#define TK    128
#define DC    32

// fp32 norm tables, computed replicating XLA's row-reduction emitter
__device__ float g_csq[NHEAD * NCODE];
__device__ float g_xsq[N_TOK * NHEAD];   // row = tok*NHEAD + h (natural x row order)
__device__ int   g_idx[NHEAD * N_TOK];

// standard XLA warp reduce: shfl_down tree 16,8,4,2,1 (lane 0 holds result)
__device__ __forceinline__ float warp_tree(float v) {
#pragma unroll
    for (int off = 16; off > 0; off >>= 1)
        v = __fadd_rn(v, __shfl_down_sync(0xFFFFFFFFu, v, off));
    return v;
}

// XLA-style row sum-of-squares over 256 contiguous floats:
//  - multiply rounded separately (multiply HLO), reduce-add separately (no FMA)
//  - vectorization x2: virtual thread t handles elements {2t, 2t+1}
//  - 128 virtual threads = 4 warps; per-warp shfl tree; cross-warp (W0+W2)+(W1+W3)
__device__ __forceinline__ float rowsq_xla(const float* __restrict__ row, int lane) {
    float W[4];
#pragma unroll
    for (int w = 0; w < 4; w++) {
        int t = lane + 32 * w;                       // virtual thread 0..127
        float2 v = *(const float2*)(row + 2 * t);
        float m0 = __fmul_rn(v.x, v.x);
        float m1 = __fmul_rn(v.y, v.y);
        float a  = __fadd_rn(m0, m1);
        W[w] = warp_tree(a);
    }
    return __fadd_rn(__fadd_rn(W[0], W[2]), __fadd_rn(W[1], W[3]));
}

__global__ void csq_kernel(const float* __restrict__ cb) {
    int warp = (blockIdx.x * blockDim.x + threadIdx.x) >> 5;
    int lane = threadIdx.x & 31;
    if (warp >= NHEAD * NCODE) return;
    float s = rowsq_xla(cb + (size_t)warp * DH, lane);
    if (lane == 0) g_csq[warp] = s;
}

__global__ void xsq_kernel(const float* __restrict__ x) {
    int warp = (blockIdx.x * blockDim.x + threadIdx.x) >> 5;
    int lane = threadIdx.x & 31;
    if (warp >= N_TOK * NHEAD) return;
    float s = rowsq_xla(x + (size_t)warp * DH, lane);
    if (lane == 0) g_xsq[warp] = s;
}

__global__ void zero_loss_kernel(float* p) { p[0] = 0.f; }

struct SmemA {
    float Xs[DC][TM];   // d-major
    float Cs[DC][TK];   // d-major
};
struct SmemB {
    float rbv[16][TM];
    int   rbi[16][TM];
};

// ---------------- pass 1: exact-fp32 GEMM (ascending FFMA chain) + argmin ----------------
__global__ __launch_bounds__(256, 2)
void vq_main(const float* __restrict__ x, const float* __restrict__ cb) {
    __shared__ union { SmemA a; SmemB b; } sm;

    const int h    = blockIdx.y;
    const int tok0 = blockIdx.x * TM;
    const int tid  = threadIdx.x;
    const int tx   = tid & 15;
    const int ty   = tid >> 4;

    const float* xbase = x  + (size_t)tok0 * 1024 + h * DH;
    const float* cbase = cb + (size_t)h * NCODE * DH;

    float xsq[8];
#pragma unroll
    for (int i = 0; i < 8; i++)
        xsq[i] = g_xsq[(size_t)(tok0 + ty * 8 + i) * NHEAD + h];

    float bestv[8];
    int   besti[8];
#pragma unroll
    for (int i = 0; i < 8; i++) { bestv[i] = 3.4e38f; besti[i] = 0x7FFFFFFF; }

    for (int kc = 0; kc < NCODE; kc += TK) {
        float acc[8][8];
#pragma unroll
        for (int i = 0; i < 8; i++)
#pragma unroll
            for (int j = 0; j < 8; j++) acc[i][j] = 0.f;

        for (int dc = 0; dc < DH; dc += DC) {
#pragma unroll
            for (int it = 0; it < 4; it++) {
                int g  = tid + it * 256;
                int t  = g >> 3;
                int dq = g & 7;
                float4 v = *(const float4*)(xbase + (size_t)t * 1024 + dc + dq * 4);
                sm.a.Xs[dq * 4 + 0][t] = v.x;
                sm.a.Xs[dq * 4 + 1][t] = v.y;
                sm.a.Xs[dq * 4 + 2][t] = v.z;
                sm.a.Xs[dq * 4 + 3][t] = v.w;
            }
#pragma unroll
            for (int it = 0; it < 4; it++) {
                int g  = tid + it * 256;
                int r  = g >> 3;
                int dq = g & 7;
                float4 v = *(const float4*)(cbase + (size_t)(kc + r) * DH + dc + dq * 4);
                sm.a.Cs[dq * 4 + 0][r] = v.x;
                sm.a.Cs[dq * 4 + 1][r] = v.y;
                sm.a.Cs[dq * 4 + 2][r] = v.z;
                sm.a.Cs[dq * 4 + 3][r] = v.w;
            }
            __syncthreads();

            // strictly ascending d => per-(i,j) FFMA chain matches cuBLAS SGEMM's
            // single-accumulator sequential accumulation
#pragma unroll 4
            for (int d = 0; d < DC; d++) {
                float4 x0 = *(const float4*)&sm.a.Xs[d][ty * 8];
                float4 x1 = *(const float4*)&sm.a.Xs[d][ty * 8 + 4];
                float4 c0 = *(const float4*)&sm.a.Cs[d][tx * 8];
                float4 c1 = *(const float4*)&sm.a.Cs[d][tx * 8 + 4];
                float xr[8] = {x0.x, x0.y, x0.z, x0.w, x1.x, x1.y, x1.z, x1.w};
                float cr[8] = {c0.x, c0.y, c0.z, c0.w, c1.x, c1.y, c1.z, c1.w};
#pragma unroll
                for (int i = 0; i < 8; i++)
#pragma unroll
                    for (int j = 0; j < 8; j++)
                        acc[i][j] = fmaf(xr[i], cr[j], acc[i][j]);
            }
            __syncthreads();
        }

        // ref chain: t1 = fl(xsq + csq); t0 = 2*dot (exact); dist = fl(t1 - t0)
#pragma unroll
        for (int j = 0; j < 8; j++) {
            int   k   = kc + tx * 8 + j;
            float csq = g_csq[h * NCODE + k];
#pragma unroll
            for (int i = 0; i < 8; i++) {
                float t1   = __fadd_rn(xsq[i], csq);
                float t0   = __fmul_rn(2.f, acc[i][j]);
                float dist = __fsub_rn(t1, t0);
                if (dist < bestv[i]) { bestv[i] = dist; besti[i] = k; }
            }
        }
    }

    // cross-thread reduction, lowest-index tie-break (jnp.argmin semantics)
#pragma unroll
    for (int i = 0; i < 8; i++) {
        sm.b.rbv[tx][ty * 8 + i] = bestv[i];
        sm.b.rbi[tx][ty * 8 + i] = besti[i];
    }
    __syncthreads();
    if (tid < TM) {
        float bv = sm.b.rbv[0][tid];
        int   bi = sm.b.rbi[0][tid];
#pragma unroll
        for (int t = 1; t < 16; t++) {
            float v  = sm.b.rbv[t][tid];
            int   ii = sm.b.rbi[t][tid];
            if (v < bv || (v == bv && ii < bi)) { bv = v; bi = ii; }
        }
        g_idx[h * N_TOK + tok0 + tid] = bi;
    }
}

// ---------------- pass 2: gather + straight-through + loss ----------------
__global__ __launch_bounds__(256)
void epilogue_kernel(const float* __restrict__ x, const float* __restrict__ cb,
                     float* __restrict__ qout, float* loss_out) {
    __shared__ float lred[8];

    const int h    = blockIdx.y;
    const int tok0 = blockIdx.x * TM;
    const int tid  = threadIdx.x;
    const float* xbase = x  + (size_t)tok0 * 1024 + h * DH;
    const float* cbase = cb + (size_t)h * NCODE * DH;

    float lsum = 0.f;
#pragma unroll 4
    for (int g = tid; g < TM * (DH / 4); g += 256) {
        int t  = g >> 6;
        int dq = g & 63;
        int k  = g_idx[h * N_TOK + tok0 + t];
        float4 c  = *(const float4*)(cbase + (size_t)k * DH + dq * 4);
        float4 xv = *(const float4*)(xbase + (size_t)t * 1024 + dq * 4);
        float dx0 = c.x - xv.x, dx1 = c.y - xv.y, dx2 = c.z - xv.z, dx3 = c.w - xv.w;
        lsum += dx0 * dx0 + dx1 * dx1 + dx2 * dx2 + dx3 * dx3;
        float* o = qout + (size_t)(tok0 + t) * 1024 + h * DH + dq * 4;  // 4B-aligned only
        o[0] = xv.x + dx0;
        o[1] = xv.y + dx1;
        o[2] = xv.z + dx2;
        o[3] = xv.w + dx3;
    }

    if (loss_out) {
#pragma unroll
        for (int off = 16; off > 0; off >>= 1)
            lsum += __shfl_down_sync(0xFFFFFFFFu, lsum, off);
        if ((tid & 31) == 0) lred[tid >> 5] = lsum;
        __syncthreads();
        if (tid == 0) {
            float s = 0.f;
#pragma unroll
            for (int w = 0; w < 8; w++) s += lred[w];
            atomicAdd(loss_out, s * (0.25f / (float)((size_t)N_TOK * 1024)));
        }
    }
}

extern "C" void kernel_launch(void* const* d_in, const int* in_sizes, int n_in,
                              void* d_out, int out_size) {
    const float* x  = (const float*)d_in[0];
    const float* cb = (const float*)d_in[1];
    float* out = (float*)d_out;

    const long long qelems = (long long)N_TOK * 1024;
    int has_loss = (out_size == (int)(qelems + 1)) ? 1 : 0;
    float* qout     = out + (has_loss ? 1 : 0);   // loss first, quantized after
    float* loss_out = has_loss ? out : (float*)0;

    // one warp per row
    csq_kernel<<<(NHEAD * NCODE * 32 + 255) / 256, 256>>>(cb);
    xsq_kernel<<<(N_TOK * NHEAD * 32 + 255) / 256, 256>>>(x);
    if (has_loss) zero_loss_kernel<<<1, 1>>>(out);

    dim3 grid(N_TOK / TM, NHEAD);
    vq_main<<<grid, 256>>>(x, cb);
    epilogue_kernel<<<grid, 256>>>(x, cb, qout, loss_out);
}

// round 12
// speedup vs baseline: 1.6785x; 1.6785x over previous
#include <cuda_runtime.h>

#define N_TOK 16384
#define NHEAD 4
#define NCODE 1024
#define DH    256
#define TM    128
#define TK    256
#define DC    32

// fp32 norm tables, computed replicating XLA's row-reduction emitter (FROZEN: bitwise-matched)
__device__ float g_csq[NHEAD * NCODE];
__device__ float g_xsq[N_TOK * NHEAD];
__device__ int   g_idx[NHEAD * N_TOK];

#define PACK_F32X2(out, lo, hi) \
    asm("mov.b64 %0, {%1, %2};" : "=l"(out) : "f"(lo), "f"(hi))
#define UNPACK_F32X2(lo, hi, in) \
    asm("mov.b64 {%0, %1}, %2;" : "=f"(lo), "=f"(hi) : "l"(in))
#define FMA_F32X2(d, a, b, c) \
    asm("fma.rn.f32x2 %0, %1, %2, %3;" : "=l"(d) : "l"(a), "l"(b), "l"(c))

// ---- FROZEN: XLA warp tree 16,8,4,2,1 ----
__device__ __forceinline__ float warp_tree(float v) {
#pragma unroll
    for (int off = 16; off > 0; off >>= 1)
        v = __fadd_rn(v, __shfl_down_sync(0xFFFFFFFFu, v, off));
    return v;
}

// ---- FROZEN: XLA row sum-of-squares (mul separate, x2 vectorized, (W0+W2)+(W1+W3)) ----
__device__ __forceinline__ float rowsq_xla(const float* __restrict__ row, int lane) {
    float W[4];
#pragma unroll
    for (int w = 0; w < 4; w++) {
        int t = lane + 32 * w;
        float2 v = *(const float2*)(row + 2 * t);
        float m0 = __fmul_rn(v.x, v.x);
        float m1 = __fmul_rn(v.y, v.y);
        float a  = __fadd_rn(m0, m1);
        W[w] = warp_tree(a);
    }
    return __fadd_rn(__fadd_rn(W[0], W[2]), __fadd_rn(W[1], W[3]));
}

__global__ void csq_kernel(const float* __restrict__ cb) {
    int warp = (blockIdx.x * blockDim.x + threadIdx.x) >> 5;
    int lane = threadIdx.x & 31;
    if (warp >= NHEAD * NCODE) return;
    float s = rowsq_xla(cb + (size_t)warp * DH, lane);
    if (lane == 0) g_csq[warp] = s;
}

__global__ void xsq_kernel(const float* __restrict__ x) {
    int warp = (blockIdx.x * blockDim.x + threadIdx.x) >> 5;
    int lane = threadIdx.x & 31;
    if (warp >= N_TOK * NHEAD) return;
    float s = rowsq_xla(x + (size_t)warp * DH, lane);
    if (lane == 0) g_xsq[warp] = s;
}

__global__ void zero_loss_kernel(float* p) { p[0] = 0.f; }

struct SmemA {
    float Xs[DC][TM];   // 16 KB, d-major
    float Cs[DC][TK];   // 32 KB, d-major
};
struct SmemB {
    float rbv[16][TM];
    int   rbi[16][TM];
};

// ---------------- pass 1: exact-fp32 GEMM via packed FFMA2 + argmin ----------------
__global__ __launch_bounds__(256, 1)
void vq_main(const float* __restrict__ x, const float* __restrict__ cb) {
    __shared__ union { SmemA a; SmemB b; } sm;

    const int h    = blockIdx.y;
    const int tok0 = blockIdx.x * TM;
    const int tid  = threadIdx.x;
    const int tx   = tid & 15;
    const int ty   = tid >> 4;

    const float* xbase = x  + (size_t)tok0 * 1024 + h * DH;
    const float* cbase = cb + (size_t)h * NCODE * DH;

    float xsq[8];
#pragma unroll
    for (int i = 0; i < 8; i++)
        xsq[i] = g_xsq[(size_t)(tok0 + ty * 8 + i) * NHEAD + h];

    float bestv[8];
    int   besti[8];
#pragma unroll
    for (int i = 0; i < 8; i++) { bestv[i] = 3.4e38f; besti[i] = 0x7FFFFFFF; }

    for (int kc = 0; kc < NCODE; kc += TK) {
        // acc2[i][g][p]: token i (= ty*8+i), code k = kc + g*64 + tx*4 + p*2 + {lo,hi}
        unsigned long long acc2[8][4][2];
#pragma unroll
        for (int i = 0; i < 8; i++)
#pragma unroll
            for (int g = 0; g < 4; g++) { acc2[i][g][0] = 0ull; acc2[i][g][1] = 0ull; }

        for (int dc = 0; dc < DH; dc += DC) {
            // X tile: 128 tok x 32 d -> d-major (4 float4 per thread)
#pragma unroll
            for (int it = 0; it < 4; it++) {
                int g  = tid + it * 256;
                int t  = g >> 3;
                int dq = g & 7;
                float4 v = *(const float4*)(xbase + (size_t)t * 1024 + dc + dq * 4);
                sm.a.Xs[dq * 4 + 0][t] = v.x;
                sm.a.Xs[dq * 4 + 1][t] = v.y;
                sm.a.Xs[dq * 4 + 2][t] = v.z;
                sm.a.Xs[dq * 4 + 3][t] = v.w;
            }
            // C tile: 256 codes x 32 d -> d-major (8 float4 per thread)
#pragma unroll
            for (int it = 0; it < 8; it++) {
                int g  = tid + it * 256;
                int r  = g >> 3;
                int dq = g & 7;
                float4 v = *(const float4*)(cbase + (size_t)(kc + r) * DH + dc + dq * 4);
                sm.a.Cs[dq * 4 + 0][r] = v.x;
                sm.a.Cs[dq * 4 + 1][r] = v.y;
                sm.a.Cs[dq * 4 + 2][r] = v.z;
                sm.a.Cs[dq * 4 + 3][r] = v.w;
            }
            __syncthreads();

#pragma unroll 2
            for (int d = 0; d < DC; d++) {
                // x: 8 tokens (two LDS.128, quarter-warp broadcast)
                float4 x0 = *(const float4*)&sm.a.Xs[d][ty * 8];
                float4 x1 = *(const float4*)&sm.a.Xs[d][ty * 8 + 4];
                float xr[8] = {x0.x, x0.y, x0.z, x0.w, x1.x, x1.y, x1.z, x1.w};
                unsigned long long xx[8];
#pragma unroll
                for (int i = 0; i < 8; i++) PACK_F32X2(xx[i], xr[i], xr[i]);

                // c: 16 codes as 4 groups of 4 (4 conflict-free LDS.128)
                unsigned long long cp[4][2];
#pragma unroll
                for (int g = 0; g < 4; g++) {
                    ulonglong2 cc = *(const ulonglong2*)&sm.a.Cs[d][g * 64 + tx * 4];
                    cp[g][0] = cc.x;   // codes tx*4+0, tx*4+1
                    cp[g][1] = cc.y;   // codes tx*4+2, tx*4+3
                }

#pragma unroll
                for (int i = 0; i < 8; i++)
#pragma unroll
                    for (int g = 0; g < 4; g++) {
                        FMA_F32X2(acc2[i][g][0], xx[i], cp[g][0], acc2[i][g][0]);
                        FMA_F32X2(acc2[i][g][1], xx[i], cp[g][1], acc2[i][g][1]);
                    }
            }
            __syncthreads();
        }

        // FROZEN dist chain: t1 = fl(xsq+csq); t0 = fl(2*dot); dist = fl(t1-t0)
#pragma unroll
        for (int g = 0; g < 4; g++)
#pragma unroll
            for (int p = 0; p < 2; p++) {
                int k0 = kc + g * 64 + tx * 4 + p * 2;
                float csq0 = g_csq[h * NCODE + k0];
                float csq1 = g_csq[h * NCODE + k0 + 1];
#pragma unroll
                for (int i = 0; i < 8; i++) {
                    float d0, d1;
                    UNPACK_F32X2(d0, d1, acc2[i][g][p]);
                    float t1a  = __fadd_rn(xsq[i], csq0);
                    float dist = __fsub_rn(t1a, __fmul_rn(2.f, d0));
                    if (dist < bestv[i]) { bestv[i] = dist; besti[i] = k0; }
                    float t1b  = __fadd_rn(xsq[i], csq1);
                    float dist2 = __fsub_rn(t1b, __fmul_rn(2.f, d1));
                    if (dist2 < bestv[i]) { bestv[i] = dist2; besti[i] = k0 + 1; }
                }
            }
    }

    // cross-thread reduction, lowest-index tie-break (jnp.argmin semantics)
#pragma unroll
    for (int i = 0; i < 8; i++) {
        sm.b.rbv[tx][ty * 8 + i] = bestv[i];
        sm.b.rbi[tx][ty * 8 + i] = besti[i];
    }
    __syncthreads();
    if (tid < TM) {
        float bv = sm.b.rbv[0][tid];
        int   bi = sm.b.rbi[0][tid];
#pragma unroll
        for (int t = 1; t < 16; t++) {
            float v  = sm.b.rbv[t][tid];
            int   ii = sm.b.rbi[t][tid];
            if (v < bv || (v == bv && ii < bi)) { bv = v; bi = ii; }
        }
        g_idx[h * N_TOK + tok0 + tid] = bi;
    }
}

// ---------------- pass 2: gather + straight-through + loss ----------------
__global__ __launch_bounds__(256)
void epilogue_kernel(const float* __restrict__ x, const float* __restrict__ cb,
                     float* __restrict__ qout, float* loss_out) {
    __shared__ float lred[8];

    const int h    = blockIdx.y;
    const int tok0 = blockIdx.x * TM;
    const int tid  = threadIdx.x;
    const float* xbase = x  + (size_t)tok0 * 1024 + h * DH;
    const float* cbase = cb + (size_t)h * NCODE * DH;

    float lsum = 0.f;
#pragma unroll 4
    for (int g = tid; g < TM * (DH / 4); g += 256) {
        int t  = g >> 6;
        int dq = g & 63;
        int k  = g_idx[h * N_TOK + tok0 + t];
        float4 c  = *(const float4*)(cbase + (size_t)k * DH + dq * 4);
        float4 xv = *(const float4*)(xbase + (size_t)t * 1024 + dq * 4);
        float dx0 = c.x - xv.x, dx1 = c.y - xv.y, dx2 = c.z - xv.z, dx3 = c.w - xv.w;
        lsum += dx0 * dx0 + dx1 * dx1 + dx2 * dx2 + dx3 * dx3;
        float* o = qout + (size_t)(tok0 + t) * 1024 + h * DH + dq * 4;  // 4B-aligned only
        o[0] = xv.x + dx0;
        o[1] = xv.y + dx1;
        o[2] = xv.z + dx2;
        o[3] = xv.w + dx3;
    }

    if (loss_out) {
#pragma unroll
        for (int off = 16; off > 0; off >>= 1)
            lsum += __shfl_down_sync(0xFFFFFFFFu, lsum, off);
        if ((tid & 31) == 0) lred[tid >> 5] = lsum;
        __syncthreads();
        if (tid == 0) {
            float s = 0.f;
#pragma unroll
            for (int w = 0; w < 8; w++) s += lred[w];
            atomicAdd(loss_out, s * (0.25f / (float)((size_t)N_TOK * 1024)));
        }
    }
}

extern "C" void kernel_launch(void* const* d_in, const int* in_sizes, int n_in,
                              void* d_out, int out_size) {
    const float* x  = (const float*)d_in[0];
    const float* cb = (const float*)d_in[1];
    float* out = (float*)d_out;

    const long long qelems = (long long)N_TOK * 1024;
    int has_loss = (out_size == (int)(qelems + 1)) ? 1 : 0;
    float* qout     = out + (has_loss ? 1 : 0);
    float* loss_out = has_loss ? out : (float*)0;

    csq_kernel<<<(NHEAD * NCODE * 32 + 255) / 256, 256>>>(cb);
    xsq_kernel<<<(N_TOK * NHEAD * 32 + 255) / 256, 256>>>(x);
    if (has_loss) zero_loss_kernel<<<1, 1>>>(out);

    dim3 grid(N_TOK / TM, NHEAD);
    vq_main<<<grid, 256>>>(x, cb);
    epilogue_kernel<<<grid, 256>>>(x, cb, qout, loss_out);
}

// round 13
// speedup vs baseline: 1.7984x; 1.0715x over previous
#include <cuda_runtime.h>

#define N_TOK 16384
#define NHEAD 4
#define NCODE 1024
#define DH    256
#define TM    64
#define TK    256
#define DC    32

// fp32 norm tables, computed replicating XLA's row-reduction emitter (FROZEN: bitwise-matched)
__device__ float g_csq[NHEAD * NCODE];
__device__ float g_xsq[N_TOK * NHEAD];
__device__ int   g_idx[NHEAD * N_TOK];

#define PACK_F32X2(out, lo, hi) \
    asm("mov.b64 %0, {%1, %2};" : "=l"(out) : "f"(lo), "f"(hi))
#define UNPACK_F32X2(lo, hi, in) \
    asm("mov.b64 {%0, %1}, %2;" : "=f"(lo), "=f"(hi) : "l"(in))
#define FMA_F32X2(d, a, b, c) \
    asm("fma.rn.f32x2 %0, %1, %2, %3;" : "=l"(d) : "l"(a), "l"(b), "l"(c))

// ---- FROZEN: XLA warp tree 16,8,4,2,1 ----
__device__ __forceinline__ float warp_tree(float v) {
#pragma unroll
    for (int off = 16; off > 0; off >>= 1)
        v = __fadd_rn(v, __shfl_down_sync(0xFFFFFFFFu, v, off));
    return v;
}

// ---- FROZEN: XLA row sum-of-squares (mul separate, x2 vectorized, (W0+W2)+(W1+W3)) ----
__device__ __forceinline__ float rowsq_xla(const float* __restrict__ row, int lane) {
    float W[4];
#pragma unroll
    for (int w = 0; w < 4; w++) {
        int t = lane + 32 * w;
        float2 v = *(const float2*)(row + 2 * t);
        float m0 = __fmul_rn(v.x, v.x);
        float m1 = __fmul_rn(v.y, v.y);
        float a  = __fadd_rn(m0, m1);
        W[w] = warp_tree(a);
    }
    return __fadd_rn(__fadd_rn(W[0], W[2]), __fadd_rn(W[1], W[3]));
}

__global__ void csq_kernel(const float* __restrict__ cb) {
    int warp = (blockIdx.x * blockDim.x + threadIdx.x) >> 5;
    int lane = threadIdx.x & 31;
    if (warp >= NHEAD * NCODE) return;
    float s = rowsq_xla(cb + (size_t)warp * DH, lane);
    if (lane == 0) g_csq[warp] = s;
}

__global__ void xsq_kernel(const float* __restrict__ x) {
    int warp = (blockIdx.x * blockDim.x + threadIdx.x) >> 5;
    int lane = threadIdx.x & 31;
    if (warp >= N_TOK * NHEAD) return;
    float s = rowsq_xla(x + (size_t)warp * DH, lane);
    if (lane == 0) g_xsq[warp] = s;
}

__global__ void zero_loss_kernel(float* p) { p[0] = 0.f; }

struct SmemA {
    float Xs[DC][TM];   // 8 KB, d-major
    float Cs[DC][TK];   // 32 KB, d-major
};
struct SmemB {
    float rbv[32][TM];  // 8 KB
    int   rbi[32][TM];  // 8 KB
};

// ---------------- pass 1: exact-fp32 GEMM via packed FFMA2 + argmin ----------------
// 256 threads, 2 CTAs/SM. Per thread: 8 tokens (ty) x 8 codes (tx).
__global__ __launch_bounds__(256, 2)
void vq_main(const float* __restrict__ x, const float* __restrict__ cb) {
    __shared__ union { SmemA a; SmemB b; } sm;

    const int h    = blockIdx.y;
    const int tok0 = blockIdx.x * TM;
    const int tid  = threadIdx.x;
    const int tx   = tid & 31;    // code group: k = kc + g*128 + tx*4 + {0..3}
    const int ty   = tid >> 5;    // token group: t = ty*8 + {0..7}

    const float* xbase = x  + (size_t)tok0 * 1024 + h * DH;
    const float* cbase = cb + (size_t)h * NCODE * DH;

    float xsq[8];
#pragma unroll
    for (int i = 0; i < 8; i++)
        xsq[i] = g_xsq[(size_t)(tok0 + ty * 8 + i) * NHEAD + h];

    float bestv[8];
    int   besti[8];
#pragma unroll
    for (int i = 0; i < 8; i++) { bestv[i] = 3.4e38f; besti[i] = 0x7FFFFFFF; }

    for (int kc = 0; kc < NCODE; kc += TK) {
        // acc2[i][g][p]: token ty*8+i, code kc + g*128 + tx*4 + p*2 + {lo,hi}
        unsigned long long acc2[8][2][2];
#pragma unroll
        for (int i = 0; i < 8; i++)
#pragma unroll
            for (int g = 0; g < 2; g++) { acc2[i][g][0] = 0ull; acc2[i][g][1] = 0ull; }

        for (int dc = 0; dc < DH; dc += DC) {
            // X tile: 64 tok x 32 d -> d-major (2 float4 per thread)
#pragma unroll
            for (int it = 0; it < 2; it++) {
                int g  = tid + it * 256;
                int t  = g >> 3;
                int dq = g & 7;
                float4 v = *(const float4*)(xbase + (size_t)t * 1024 + dc + dq * 4);
                sm.a.Xs[dq * 4 + 0][t] = v.x;
                sm.a.Xs[dq * 4 + 1][t] = v.y;
                sm.a.Xs[dq * 4 + 2][t] = v.z;
                sm.a.Xs[dq * 4 + 3][t] = v.w;
            }
            // C tile: 256 codes x 32 d -> d-major (8 float4 per thread)
#pragma unroll
            for (int it = 0; it < 8; it++) {
                int g  = tid + it * 256;
                int r  = g >> 3;
                int dq = g & 7;
                float4 v = *(const float4*)(cbase + (size_t)(kc + r) * DH + dc + dq * 4);
                sm.a.Cs[dq * 4 + 0][r] = v.x;
                sm.a.Cs[dq * 4 + 1][r] = v.y;
                sm.a.Cs[dq * 4 + 2][r] = v.z;
                sm.a.Cs[dq * 4 + 3][r] = v.w;
            }
            __syncthreads();

            for (int d = 0; d < DC; d++) {
                // c: 8 codes as 2 conflict-free LDS.128 (16B lane stride)
                ulonglong2 cc0 = *(const ulonglong2*)&sm.a.Cs[d][tx * 4];
                ulonglong2 cc1 = *(const ulonglong2*)&sm.a.Cs[d][128 + tx * 4];
                // x: 8 tokens, full-warp broadcast LDS.128 (all lanes same ty)
                float4 x0 = *(const float4*)&sm.a.Xs[d][ty * 8];
                float4 x1 = *(const float4*)&sm.a.Xs[d][ty * 8 + 4];
                float xr[8] = {x0.x, x0.y, x0.z, x0.w, x1.x, x1.y, x1.z, x1.w};
                unsigned long long xx[8];
#pragma unroll
                for (int i = 0; i < 8; i++) PACK_F32X2(xx[i], xr[i], xr[i]);

#pragma unroll
                for (int i = 0; i < 8; i++) {
                    FMA_F32X2(acc2[i][0][0], xx[i], cc0.x, acc2[i][0][0]);
                    FMA_F32X2(acc2[i][0][1], xx[i], cc0.y, acc2[i][0][1]);
                    FMA_F32X2(acc2[i][1][0], xx[i], cc1.x, acc2[i][1][0]);
                    FMA_F32X2(acc2[i][1][1], xx[i], cc1.y, acc2[i][1][1]);
                }
            }
            __syncthreads();
        }

        // FROZEN dist chain: t1 = fl(xsq+csq); t0 = fl(2*dot); dist = fl(t1-t0)
        // ascending k within thread: g then p then lo/hi
#pragma unroll
        for (int g = 0; g < 2; g++)
#pragma unroll
            for (int p = 0; p < 2; p++) {
                int k0 = kc + g * 128 + tx * 4 + p * 2;
                float csq0 = g_csq[h * NCODE + k0];
                float csq1 = g_csq[h * NCODE + k0 + 1];
#pragma unroll
                for (int i = 0; i < 8; i++) {
                    float d0, d1;
                    UNPACK_F32X2(d0, d1, acc2[i][g][p]);
                    float t1a   = __fadd_rn(xsq[i], csq0);
                    float dist  = __fsub_rn(t1a, __fmul_rn(2.f, d0));
                    if (dist < bestv[i]) { bestv[i] = dist; besti[i] = k0; }
                    float t1b   = __fadd_rn(xsq[i], csq1);
                    float dist2 = __fsub_rn(t1b, __fmul_rn(2.f, d1));
                    if (dist2 < bestv[i]) { bestv[i] = dist2; besti[i] = k0 + 1; }
                }
            }
    }

    // cross-thread reduction over 32 tx slots, lowest-index tie-break
#pragma unroll
    for (int i = 0; i < 8; i++) {
        sm.b.rbv[tx][ty * 8 + i] = bestv[i];
        sm.b.rbi[tx][ty * 8 + i] = besti[i];
    }
    __syncthreads();
    if (tid < TM) {
        float bv = sm.b.rbv[0][tid];
        int   bi = sm.b.rbi[0][tid];
#pragma unroll
        for (int t = 1; t < 32; t++) {
            float v  = sm.b.rbv[t][tid];
            int   ii = sm.b.rbi[t][tid];
            if (v < bv || (v == bv && ii < bi)) { bv = v; bi = ii; }
        }
        g_idx[h * N_TOK + tok0 + tid] = bi;
    }
}

// ---------------- pass 2: gather + straight-through + loss ----------------
__global__ __launch_bounds__(256)
void epilogue_kernel(const float* __restrict__ x, const float* __restrict__ cb,
                     float* __restrict__ qout, float* loss_out) {
    __shared__ float lred[8];

    const int h    = blockIdx.y;
    const int tok0 = blockIdx.x * TM;
    const int tid  = threadIdx.x;
    const float* xbase = x  + (size_t)tok0 * 1024 + h * DH;
    const float* cbase = cb + (size_t)h * NCODE * DH;

    float lsum = 0.f;
#pragma unroll 4
    for (int g = tid; g < TM * (DH / 4); g += 256) {
        int t  = g >> 6;
        int dq = g & 63;
        int k  = g_idx[h * N_TOK + tok0 + t];
        float4 c  = *(const float4*)(cbase + (size_t)k * DH + dq * 4);
        float4 xv = *(const float4*)(xbase + (size_t)t * 1024 + dq * 4);
        float dx0 = c.x - xv.x, dx1 = c.y - xv.y, dx2 = c.z - xv.z, dx3 = c.w - xv.w;
        lsum += dx0 * dx0 + dx1 * dx1 + dx2 * dx2 + dx3 * dx3;
        float* o = qout + (size_t)(tok0 + t) * 1024 + h * DH + dq * 4;  // 4B-aligned only
        o[0] = xv.x + dx0;
        o[1] = xv.y + dx1;
        o[2] = xv.z + dx2;
        o[3] = xv.w + dx3;
    }

    if (loss_out) {
#pragma unroll
        for (int off = 16; off > 0; off >>= 1)
            lsum += __shfl_down_sync(0xFFFFFFFFu, lsum, off);
        if ((tid & 31) == 0) lred[tid >> 5] = lsum;
        __syncthreads();
        if (tid == 0) {
            float s = 0.f;
#pragma unroll
            for (int w = 0; w < 8; w++) s += lred[w];
            atomicAdd(loss_out, s * (0.25f / (float)((size_t)N_TOK * 1024)));
        }
    }
}

extern "C" void kernel_launch(void* const* d_in, const int* in_sizes, int n_in,
                              void* d_out, int out_size) {
    const float* x  = (const float*)d_in[0];
    const float* cb = (const float*)d_in[1];
    float* out = (float*)d_out;

    const long long qelems = (long long)N_TOK * 1024;
    int has_loss = (out_size == (int)(qelems + 1)) ? 1 : 0;
    float* qout     = out + (has_loss ? 1 : 0);
    float* loss_out = has_loss ? out : (float*)0;

    csq_kernel<<<(NHEAD * NCODE * 32 + 255) / 256, 256>>>(cb);
    xsq_kernel<<<(N_TOK * NHEAD * 32 + 255) / 256, 256>>>(x);
    if (has_loss) zero_loss_kernel<<<1, 1>>>(out);

    dim3 grid(N_TOK / TM, NHEAD);
    vq_main<<<grid, 256>>>(x, cb);
    epilogue_kernel<<<grid, 256>>>(x, cb, qout, loss_out);
}

// round 14
// speedup vs baseline: 2.3912x; 1.3296x over previous
#include <cuda_runtime.h>
#include <cstdint>

#define N_TOK 16384
#define NHEAD 4
#define NCODE 1024
#define DH    256
#define EPS   4.0f

// fp32 norm tables (FROZEN: bitwise-matched to XLA reduction emitter)
__device__ float g_csq[NHEAD * NCODE];
__device__ float g_xsq[N_TOK * NHEAD];
__device__ int   g_idx[NHEAD * N_TOK];
// screen results
__device__ int   g_cand[NHEAD * N_TOK * 16];
__device__ int   g_cnt [NHEAD * N_TOK];

__device__ __forceinline__ float to_tf32(float v) {
    float o;
    asm("cvt.rna.tf32.f32 %0, %1;" : "=f"(o) : "f"(v));
    return o;
}

// ---- FROZEN: XLA warp tree 16,8,4,2,1 ----
__device__ __forceinline__ float warp_tree(float v) {
#pragma unroll
    for (int off = 16; off > 0; off >>= 1)
        v = __fadd_rn(v, __shfl_down_sync(0xFFFFFFFFu, v, off));
    return v;
}

// ---- FROZEN: XLA row sum-of-squares ----
__device__ __forceinline__ float rowsq_xla(const float* __restrict__ row, int lane) {
    float W[4];
#pragma unroll
    for (int w = 0; w < 4; w++) {
        int t = lane + 32 * w;
        float2 v = *(const float2*)(row + 2 * t);
        float m0 = __fmul_rn(v.x, v.x);
        float m1 = __fmul_rn(v.y, v.y);
        float a  = __fadd_rn(m0, m1);
        W[w] = warp_tree(a);
    }
    return __fadd_rn(__fadd_rn(W[0], W[2]), __fadd_rn(W[1], W[3]));
}

__global__ void csq_kernel(const float* __restrict__ cb) {
    int warp = (blockIdx.x * blockDim.x + threadIdx.x) >> 5;
    int lane = threadIdx.x & 31;
    if (warp >= NHEAD * NCODE) return;
    float s = rowsq_xla(cb + (size_t)warp * DH, lane);
    if (lane == 0) g_csq[warp] = s;
}

__global__ void xsq_kernel(const float* __restrict__ x) {
    int warp = (blockIdx.x * blockDim.x + threadIdx.x) >> 5;
    int lane = threadIdx.x & 31;
    if (warp >= N_TOK * NHEAD) return;
    float s = rowsq_xla(x + (size_t)warp * DH, lane);
    if (lane == 0) g_xsq[warp] = s;
}

__global__ void zero_loss_kernel(float* p) { p[0] = 0.f; }

// ---------------- Phase A: tf32 tensor screen ----------------
// Block: 512 thr (16 warps), 128 tokens x (4 x 256)-code blocks, K=256.
// Warp w: tg = w>>1 (16 tokens), cg = w&1 (128 codes per 256-code block).
__global__ __launch_bounds__(512, 1)
void vq_screen(const float* __restrict__ x, const float* __restrict__ cb) {
    __shared__ float Xs[16][136];            // [k][tok], stride 136 -> banks 8k+tok
    __shared__ float Cs[16][264];            // [k][code], stride 264 -> banks 8k+code
    __shared__ unsigned tokmin[128];
    __shared__ int cnt[128];
    __shared__ int cand[128][16];

    const int h    = blockIdx.y;
    const int tok0 = blockIdx.x * 128;
    const int tid  = threadIdx.x;
    const int warp = tid >> 5, lane = tid & 31;
    const int tg   = warp >> 1, cg = warp & 1;
    const int gid  = lane >> 2, tig = lane & 3;

    const float* xbase = x  + (size_t)tok0 * 1024 + h * DH;
    const float* cbase = cb + (size_t)h * NCODE * DH;

    if (tid < 128) { tokmin[tid] = 0x7F800000u; cnt[tid] = 0; }
    for (int i = tid; i < 128 * 16; i += 512) (&cand[0][0])[i] = 0;
    __syncthreads();

    const int tl0 = tg * 16 + gid;           // token row 0 (local)
    const int tl1 = tl0 + 8;                 // token row 1
    const float xsq0 = g_xsq[(size_t)(tok0 + tl0) * NHEAD + h];
    const float xsq1 = g_xsq[(size_t)(tok0 + tl1) * NHEAD + h];

    for (int cbi = 0; cbi < 4; cbi++) {
        float acc[16][4];
#pragma unroll
        for (int nt = 0; nt < 16; nt++)
#pragma unroll
            for (int c = 0; c < 4; c++) acc[nt][c] = 0.f;

        for (int kc = 0; kc < DH; kc += 16) {
            // stage X: 128 tok x 16 d (1 float4/thread), tf32-rounded, d-major
            {
                int t = tid >> 2, dq = tid & 3;
                float4 v = *(const float4*)(xbase + (size_t)t * 1024 + kc + dq * 4);
                Xs[dq * 4 + 0][t] = to_tf32(v.x);
                Xs[dq * 4 + 1][t] = to_tf32(v.y);
                Xs[dq * 4 + 2][t] = to_tf32(v.z);
                Xs[dq * 4 + 3][t] = to_tf32(v.w);
            }
            // stage C: 256 codes x 16 d (2 float4/thread)
#pragma unroll
            for (int it = 0; it < 2; it++) {
                int g = tid + it * 512;
                int r = g >> 2, dq = g & 3;
                float4 v = *(const float4*)(cbase + (size_t)(cbi * 256 + r) * DH + kc + dq * 4);
                Cs[dq * 4 + 0][r] = to_tf32(v.x);
                Cs[dq * 4 + 1][r] = to_tf32(v.y);
                Cs[dq * 4 + 2][r] = to_tf32(v.z);
                Cs[dq * 4 + 3][r] = to_tf32(v.w);
            }
            __syncthreads();

#pragma unroll
            for (int ks = 0; ks < 2; ks++) {
                int k0 = ks * 8;
                uint32_t a0 = __float_as_uint(Xs[k0 + tig    ][tg * 16 + gid]);
                uint32_t a1 = __float_as_uint(Xs[k0 + tig    ][tg * 16 + gid + 8]);
                uint32_t a2 = __float_as_uint(Xs[k0 + tig + 4][tg * 16 + gid]);
                uint32_t a3 = __float_as_uint(Xs[k0 + tig + 4][tg * 16 + gid + 8]);
#pragma unroll
                for (int nt = 0; nt < 16; nt++) {
                    uint32_t b0 = __float_as_uint(Cs[k0 + tig    ][cg * 128 + nt * 8 + gid]);
                    uint32_t b1 = __float_as_uint(Cs[k0 + tig + 4][cg * 128 + nt * 8 + gid]);
                    asm volatile(
                        "mma.sync.aligned.m16n8k8.row.col.f32.tf32.tf32.f32 "
                        "{%0,%1,%2,%3}, {%4,%5,%6,%7}, {%8,%9}, {%0,%1,%2,%3};"
                        : "+f"(acc[nt][0]), "+f"(acc[nt][1]),
                          "+f"(acc[nt][2]), "+f"(acc[nt][3])
                        : "r"(a0), "r"(a1), "r"(a2), "r"(a3), "r"(b0), "r"(b1));
                }
            }
            __syncthreads();
        }

        // sweep 1: thread-local min per token row -> smem atomicMin
        float m0 = 3.4e38f, m1 = 3.4e38f;
#pragma unroll
        for (int nt = 0; nt < 16; nt++)
#pragma unroll
            for (int c = 0; c < 2; c++) {
                int k = cbi * 256 + cg * 128 + nt * 8 + 2 * tig + c;
                float csqv = g_csq[h * NCODE + k];
                float d0 = xsq0 + csqv - 2.f * acc[nt][c];
                float d1 = xsq1 + csqv - 2.f * acc[nt][c + 2];
                m0 = fminf(m0, d0);
                m1 = fminf(m1, d1);
            }
        atomicMin(&tokmin[tl0], __float_as_uint(m0));
        atomicMin(&tokmin[tl1], __float_as_uint(m1));
        __syncthreads();

        // sweep 2: collect candidates within EPS of settled running min
        float th0 = __uint_as_float(tokmin[tl0]) + EPS;
        float th1 = __uint_as_float(tokmin[tl1]) + EPS;
#pragma unroll
        for (int nt = 0; nt < 16; nt++)
#pragma unroll
            for (int c = 0; c < 2; c++) {
                int k = cbi * 256 + cg * 128 + nt * 8 + 2 * tig + c;
                float csqv = g_csq[h * NCODE + k];
                float d0 = xsq0 + csqv - 2.f * acc[nt][c];
                float d1 = xsq1 + csqv - 2.f * acc[nt][c + 2];
                if (d0 <= th0) {
                    int pos = atomicAdd(&cnt[tl0], 1);
                    if (pos < 16) cand[tl0][pos] = k;
                }
                if (d1 <= th1) {
                    int pos = atomicAdd(&cnt[tl1], 1);
                    if (pos < 16) cand[tl1][pos] = k;
                }
            }
        __syncthreads();
    }

    if (tid < 128) {
        int tokg = h * N_TOK + tok0 + tid;
        g_cnt[tokg] = cnt[tid];
#pragma unroll
        for (int j = 0; j < 16; j++) g_cand[(size_t)tokg * 16 + j] = cand[tid][j];
    }
}

// ---------------- Phase B: exact rescore (FROZEN arithmetic) ----------------
__global__ __launch_bounds__(64)
void vq_rescore(const float* __restrict__ x, const float* __restrict__ cb) {
    __shared__ float xs[DH];
    __shared__ float sv[64];
    __shared__ int   si[64];

    const int tok = blockIdx.x;
    const int h   = blockIdx.y;
    const int tid = threadIdx.x;

    const float* xrow = x + ((size_t)tok * NHEAD + h) * DH;
    ((float4*)xs)[tid] = ((const float4*)xrow)[tid];
    __syncthreads();

    const int   tokg = h * N_TOK + tok;
    const int   n    = g_cnt[tokg];
    const float xsqv = g_xsq[(size_t)tok * NHEAD + h];

    float bv = 3.4e38f;
    int   bi = 0x7FFFFFFF;

    if (n <= 16) {
        for (int j = tid; j < n; j += 64) {
            int k = g_cand[(size_t)tokg * 16 + j];
            const float* crow = cb + ((size_t)h * NCODE + k) * DH;
            float a = 0.f;
#pragma unroll 8
            for (int d = 0; d < DH; d++) a = fmaf(xs[d], crow[d], a);
            float t1   = __fadd_rn(xsqv, g_csq[h * NCODE + k]);
            float dist = __fsub_rn(t1, __fmul_rn(2.f, a));
            if (dist < bv || (dist == bv && k < bi)) { bv = dist; bi = k; }
        }
    } else {
        for (int k = tid; k < NCODE; k += 64) {
            const float* crow = cb + ((size_t)h * NCODE + k) * DH;
            float a = 0.f;
#pragma unroll 8
            for (int d = 0; d < DH; d++) a = fmaf(xs[d], crow[d], a);
            float t1   = __fadd_rn(xsqv, g_csq[h * NCODE + k]);
            float dist = __fsub_rn(t1, __fmul_rn(2.f, a));
            if (dist < bv || (dist == bv && k < bi)) { bv = dist; bi = k; }
        }
    }

    sv[tid] = bv; si[tid] = bi;
    __syncthreads();
#pragma unroll
    for (int off = 32; off > 0; off >>= 1) {
        if (tid < off) {
            float v = sv[tid + off]; int ii = si[tid + off];
            if (v < sv[tid] || (v == sv[tid] && ii < si[tid])) { sv[tid] = v; si[tid] = ii; }
        }
        __syncthreads();
    }
    if (tid == 0) g_idx[tokg] = si[0];
}

// ---------------- epilogue: gather + straight-through + loss ----------------
#define TME 64
__global__ __launch_bounds__(256)
void epilogue_kernel(const float* __restrict__ x, const float* __restrict__ cb,
                     float* __restrict__ qout, float* loss_out) {
    __shared__ float lred[8];

    const int h    = blockIdx.y;
    const int tok0 = blockIdx.x * TME;
    const int tid  = threadIdx.x;
    const float* xbase = x  + (size_t)tok0 * 1024 + h * DH;
    const float* cbase = cb + (size_t)h * NCODE * DH;

    float lsum = 0.f;
#pragma unroll 4
    for (int g = tid; g < TME * (DH / 4); g += 256) {
        int t  = g >> 6;
        int dq = g & 63;
        int k  = g_idx[h * N_TOK + tok0 + t];
        float4 c  = *(const float4*)(cbase + (size_t)k * DH + dq * 4);
        float4 xv = *(const float4*)(xbase + (size_t)t * 1024 + dq * 4);
        float dx0 = c.x - xv.x, dx1 = c.y - xv.y, dx2 = c.z - xv.z, dx3 = c.w - xv.w;
        lsum += dx0 * dx0 + dx1 * dx1 + dx2 * dx2 + dx3 * dx3;
        float* o = qout + (size_t)(tok0 + t) * 1024 + h * DH + dq * 4;  // 4B-aligned only
        o[0] = xv.x + dx0;
        o[1] = xv.y + dx1;
        o[2] = xv.z + dx2;
        o[3] = xv.w + dx3;
    }

    if (loss_out) {
#pragma unroll
        for (int off = 16; off > 0; off >>= 1)
            lsum += __shfl_down_sync(0xFFFFFFFFu, lsum, off);
        if ((tid & 31) == 0) lred[tid >> 5] = lsum;
        __syncthreads();
        if (tid == 0) {
            float s = 0.f;
#pragma unroll
            for (int w = 0; w < 8; w++) s += lred[w];
            atomicAdd(loss_out, s * (0.25f / (float)((size_t)N_TOK * 1024)));
        }
    }
}

extern "C" void kernel_launch(void* const* d_in, const int* in_sizes, int n_in,
                              void* d_out, int out_size) {
    const float* x  = (const float*)d_in[0];
    const float* cb = (const float*)d_in[1];
    float* out = (float*)d_out;

    const long long qelems = (long long)N_TOK * 1024;
    int has_loss = (out_size == (int)(qelems + 1)) ? 1 : 0;
    float* qout     = out + (has_loss ? 1 : 0);
    float* loss_out = has_loss ? out : (float*)0;

    csq_kernel<<<(NHEAD * NCODE * 32 + 255) / 256, 256>>>(cb);
    xsq_kernel<<<(N_TOK * NHEAD * 32 + 255) / 256, 256>>>(x);
    if (has_loss) zero_loss_kernel<<<1, 1>>>(out);

    dim3 sgrid(N_TOK / 128, NHEAD);
    vq_screen<<<sgrid, 512>>>(x, cb);

    dim3 rgrid(N_TOK, NHEAD);
    vq_rescore<<<rgrid, 64>>>(x, cb);

    dim3 egrid(N_TOK / TME, NHEAD);
    epilogue_kernel<<<egrid, 256>>>(x, cb, qout, loss_out);
}

// round 15
// speedup vs baseline: 2.4784x; 1.0365x over previous
#include <cuda_runtime.h>
#include <cstdint>

#define N_TOK 16384
#define NHEAD 4
#define NCODE 1024
#define DH    256
#define EPS   4.0f

// fp32 norm tables (FROZEN: bitwise-matched to XLA reduction emitter)
__device__ float g_csq[NHEAD * NCODE];
__device__ float g_xsq[N_TOK * NHEAD];
__device__ int   g_idx[NHEAD * N_TOK];
// screen results
__device__ int   g_cand[NHEAD * N_TOK * 16];
__device__ int   g_cnt [NHEAD * N_TOK];

__device__ __forceinline__ float to_tf32(float v) {
    float o;
    asm("cvt.rna.tf32.f32 %0, %1;" : "=f"(o) : "f"(v));
    return o;
}

// ---- FROZEN: XLA warp tree 16,8,4,2,1 ----
__device__ __forceinline__ float warp_tree(float v) {
#pragma unroll
    for (int off = 16; off > 0; off >>= 1)
        v = __fadd_rn(v, __shfl_down_sync(0xFFFFFFFFu, v, off));
    return v;
}

// ---- FROZEN: XLA row sum-of-squares ----
__device__ __forceinline__ float rowsq_xla(const float* __restrict__ row, int lane) {
    float W[4];
#pragma unroll
    for (int w = 0; w < 4; w++) {
        int t = lane + 32 * w;
        float2 v = *(const float2*)(row + 2 * t);
        float m0 = __fmul_rn(v.x, v.x);
        float m1 = __fmul_rn(v.y, v.y);
        float a  = __fadd_rn(m0, m1);
        W[w] = warp_tree(a);
    }
    return __fadd_rn(__fadd_rn(W[0], W[2]), __fadd_rn(W[1], W[3]));
}

__global__ void csq_kernel(const float* __restrict__ cb) {
    int warp = (blockIdx.x * blockDim.x + threadIdx.x) >> 5;
    int lane = threadIdx.x & 31;
    if (warp >= NHEAD * NCODE) return;
    float s = rowsq_xla(cb + (size_t)warp * DH, lane);
    if (lane == 0) g_csq[warp] = s;
}

__global__ void xsq_kernel(const float* __restrict__ x) {
    int warp = (blockIdx.x * blockDim.x + threadIdx.x) >> 5;
    int lane = threadIdx.x & 31;
    if (warp >= N_TOK * NHEAD) return;
    float s = rowsq_xla(x + (size_t)warp * DH, lane);
    if (lane == 0) g_xsq[warp] = s;
}

__global__ void zero_loss_kernel(float* p) { p[0] = 0.f; }

// ---------------- Phase A: tf32 tensor screen (fragment-layout smem) ----------------
// 512 thr / 16 warps. Warp w: tg=w>>1 (16 tokens), cg=w&1 (128 codes of 256-block).
// XBuf: all 256 d in a-fragment order (128 KB). CBuf: 2 ping-pong half-chunk
// buffers in b-fragment order (2 x 16 KB). Dynamic smem total 160 KB.
__global__ __launch_bounds__(512, 1)
void vq_screen(const float* __restrict__ x, const float* __restrict__ cb) {
    extern __shared__ float dsm[];
    float* XBuf = dsm;                 // 32768 floats
    float* CBuf = dsm + 32768;         // 2 * 4096 floats

    __shared__ unsigned tokmin[128];
    __shared__ int cnt[128];
    __shared__ int cand[128][16];

    const int h    = blockIdx.y;
    const int tok0 = blockIdx.x * 128;
    const int tid  = threadIdx.x;
    const int warp = tid >> 5, lane = tid & 31;
    const int tg   = warp >> 1, cg = warp & 1;
    const int gid  = lane >> 2, tig = lane & 3;

    const float* xbase = x  + (size_t)tok0 * 1024 + h * DH;
    const float* cbase = cb + (size_t)h * NCODE * DH;

    if (tid < 128) { tokmin[tid] = 0x7F800000u; cnt[tid] = 0; }
    for (int i = tid; i < 128 * 16; i += 512) (&cand[0][0])[i] = 0;

    // ---- stage ALL of X into a-fragment layout (once) ----
    {
        int t  = tid >> 2;                 // token 0..127
        int r  = t & 15, tgs = t >> 4;
        const float* xrow = xbase + (size_t)t * 1024;
#pragma unroll
        for (int q = 0; q < 16; q++) {
            int d0 = (tid & 3) * 64 + q * 4;
            float4 v = *(const float4*)(xrow + d0);
            int kc8 = d0 >> 3;
            int c8  = d0 & 7;              // 0 or 4
            int slot = (r >> 3) + ((c8 >> 2) << 1);
            float* bp = XBuf + (size_t)((tgs * 32 + kc8) * 32) * 4;
            int lb = (r & 7) * 4;
            bp[(lb + 0) * 4 + slot] = to_tf32(v.x);
            bp[(lb + 1) * 4 + slot] = to_tf32(v.y);
            bp[(lb + 2) * 4 + slot] = to_tf32(v.z);
            bp[(lb + 3) * 4 + slot] = to_tf32(v.w);
        }
    }

    const int tl0  = tg * 16 + gid;
    const int tl1  = tl0 + 8;
    const float xsq0 = g_xsq[(size_t)(tok0 + tl0) * NHEAD + h];
    const float xsq1 = g_xsq[(size_t)(tok0 + tl1) * NHEAD + h];

    // C staging coords for this thread (code n, d-half part)
    const int n_    = tid >> 1;
    const int part  = tid & 1;
    const int cgs   = n_ >> 7;
    const int nls   = n_ & 127;
    const int nts   = nls >> 3;
    const int gids  = nls & 7;
    const int npr   = nts >> 1;
    const int sbase = (nts & 1) * 2;
    const float* crow = cbase + (size_t)n_ * DH + part * 8;

    float acc[16][4];
#pragma unroll
    for (int nt = 0; nt < 16; nt++)
#pragma unroll
        for (int c = 0; c < 4; c++) acc[nt][c] = 0.f;

    // prologue: load half-chunk 0 (cbi 0, hc 0)
    float4 r0 = *(const float4*)(crow);
    float4 r1 = *(const float4*)(crow + 4);

    for (int idx = 0; idx < 64; idx++) {
        const int cbi = idx >> 4;
        const int hc  = idx & 15;
        const int b   = idx & 1;

        // STS current regs in b-fragment layout
        {
            float* cbp = CBuf + b * 4096 + (size_t)(((cgs * 2 + part) * 8 + npr) * 128);
            int lb = gids * 4;
            cbp[(lb + 0) * 4 + sbase + 0] = to_tf32(r0.x);
            cbp[(lb + 1) * 4 + sbase + 0] = to_tf32(r0.y);
            cbp[(lb + 2) * 4 + sbase + 0] = to_tf32(r0.z);
            cbp[(lb + 3) * 4 + sbase + 0] = to_tf32(r0.w);
            cbp[(lb + 0) * 4 + sbase + 1] = to_tf32(r1.x);
            cbp[(lb + 1) * 4 + sbase + 1] = to_tf32(r1.y);
            cbp[(lb + 2) * 4 + sbase + 1] = to_tf32(r1.z);
            cbp[(lb + 3) * 4 + sbase + 1] = to_tf32(r1.w);
        }
        // issue next LDG early (overlaps with barrier + MMA)
        if (idx < 63) {
            int idn = idx + 1;
            const float* p = crow + (size_t)((idn >> 4)) * 256 * DH + (idn & 15) * 16;
            r0 = *(const float4*)(p);
            r1 = *(const float4*)(p + 4);
        }
        __syncthreads();

        // MMA over this half-chunk: 2 k8-steps
#pragma unroll
        for (int kc8h = 0; kc8h < 2; kc8h++) {
            float4 av = ((const float4*)XBuf)[(tg * 32 + hc * 2 + kc8h) * 32 + lane];
            uint32_t a0 = __float_as_uint(av.x), a1 = __float_as_uint(av.y);
            uint32_t a2 = __float_as_uint(av.z), a3 = __float_as_uint(av.w);
            const float4* cf = (const float4*)(CBuf + b * 4096) + (cg * 2 + kc8h) * 8 * 32;
#pragma unroll
            for (int np = 0; np < 8; np++) {
                float4 bv = cf[np * 32 + lane];
                uint32_t b0 = __float_as_uint(bv.x), b1 = __float_as_uint(bv.y);
                uint32_t b2 = __float_as_uint(bv.z), b3 = __float_as_uint(bv.w);
                asm volatile(
                    "mma.sync.aligned.m16n8k8.row.col.f32.tf32.tf32.f32 "
                    "{%0,%1,%2,%3}, {%4,%5,%6,%7}, {%8,%9}, {%0,%1,%2,%3};"
                    : "+f"(acc[2*np][0]), "+f"(acc[2*np][1]),
                      "+f"(acc[2*np][2]), "+f"(acc[2*np][3])
                    : "r"(a0), "r"(a1), "r"(a2), "r"(a3), "r"(b0), "r"(b1));
                asm volatile(
                    "mma.sync.aligned.m16n8k8.row.col.f32.tf32.tf32.f32 "
                    "{%0,%1,%2,%3}, {%4,%5,%6,%7}, {%8,%9}, {%0,%1,%2,%3};"
                    : "+f"(acc[2*np+1][0]), "+f"(acc[2*np+1][1]),
                      "+f"(acc[2*np+1][2]), "+f"(acc[2*np+1][3])
                    : "r"(a0), "r"(a1), "r"(a2), "r"(a3), "r"(b2), "r"(b3));
            }
        }

        if (hc == 15) {
            // sweep 1: thread-local min -> smem atomicMin
            float m0 = 3.4e38f, m1 = 3.4e38f;
#pragma unroll
            for (int nt = 0; nt < 16; nt++)
#pragma unroll
                for (int c = 0; c < 2; c++) {
                    int k = cbi * 256 + cg * 128 + nt * 8 + 2 * tig + c;
                    float csqv = g_csq[h * NCODE + k];
                    m0 = fminf(m0, xsq0 + csqv - 2.f * acc[nt][c]);
                    m1 = fminf(m1, xsq1 + csqv - 2.f * acc[nt][c + 2]);
                }
            atomicMin(&tokmin[tl0], __float_as_uint(m0));
            atomicMin(&tokmin[tl1], __float_as_uint(m1));
            __syncthreads();

            // sweep 2: collect candidates within EPS of running min
            float th0 = __uint_as_float(tokmin[tl0]) + EPS;
            float th1 = __uint_as_float(tokmin[tl1]) + EPS;
#pragma unroll
            for (int nt = 0; nt < 16; nt++)
#pragma unroll
                for (int c = 0; c < 2; c++) {
                    int k = cbi * 256 + cg * 128 + nt * 8 + 2 * tig + c;
                    float csqv = g_csq[h * NCODE + k];
                    float d0 = xsq0 + csqv - 2.f * acc[nt][c];
                    float d1 = xsq1 + csqv - 2.f * acc[nt][c + 2];
                    if (d0 <= th0) {
                        int pos = atomicAdd(&cnt[tl0], 1);
                        if (pos < 16) cand[tl0][pos] = k;
                    }
                    if (d1 <= th1) {
                        int pos = atomicAdd(&cnt[tl1], 1);
                        if (pos < 16) cand[tl1][pos] = k;
                    }
                }
            __syncthreads();

#pragma unroll
            for (int nt = 0; nt < 16; nt++)
#pragma unroll
                for (int c = 0; c < 4; c++) acc[nt][c] = 0.f;
        }
    }

    if (tid < 128) {
        int tokg = h * N_TOK + tok0 + tid;
        g_cnt[tokg] = cnt[tid];
#pragma unroll
        for (int j = 0; j < 16; j++) g_cand[(size_t)tokg * 16 + j] = cand[tid][j];
    }
}

// ---------------- Phase B: exact rescore (FROZEN serial chain per candidate) ----------------
// 256 thr = 8 tokens x 32 lanes; candidate-per-lane; shfl reduce w/ lowest-index ties.
__global__ __launch_bounds__(256)
void vq_rescore(const float* __restrict__ x, const float* __restrict__ cb) {
    const int h    = blockIdx.y;
    const int tok  = blockIdx.x * 8 + (threadIdx.x >> 5);
    const int lane = threadIdx.x & 31;

    const int   tokg = h * N_TOK + tok;
    const int   n    = g_cnt[tokg];
    const float xsqv = g_xsq[(size_t)tok * NHEAD + h];
    const float* xrow = x + ((size_t)tok * NHEAD + h) * DH;

    float bv = 3.4e38f;
    int   bi = 0x7FFFFFFF;

    auto score = [&](int k) {
        const float* crow = cb + ((size_t)h * NCODE + k) * DH;
        float a = 0.f;
#pragma unroll 8
        for (int d4 = 0; d4 < DH / 4; d4++) {
            float4 xv = *(const float4*)(xrow + d4 * 4);
            float4 cv = *(const float4*)(crow + d4 * 4);
            a = fmaf(xv.x, cv.x, a);
            a = fmaf(xv.y, cv.y, a);
            a = fmaf(xv.z, cv.z, a);
            a = fmaf(xv.w, cv.w, a);
        }
        float t1   = __fadd_rn(xsqv, g_csq[h * NCODE + k]);
        float dist = __fsub_rn(t1, __fmul_rn(2.f, a));
        if (dist < bv || (dist == bv && k < bi)) { bv = dist; bi = k; }
    };

    if (n <= 16) {
        if (lane < n) score(g_cand[(size_t)tokg * 16 + lane]);
    } else {
        for (int k = lane; k < NCODE; k += 32) score(k);
    }

#pragma unroll
    for (int off = 16; off > 0; off >>= 1) {
        float vo = __shfl_down_sync(0xFFFFFFFFu, bv, off);
        int   io = __shfl_down_sync(0xFFFFFFFFu, bi, off);
        if (vo < bv || (vo == bv && io < bi)) { bv = vo; bi = io; }
    }
    if (lane == 0) g_idx[tokg] = bi;
}

// ---------------- epilogue: gather + straight-through + loss ----------------
#define TME 64
__global__ __launch_bounds__(256)
void epilogue_kernel(const float* __restrict__ x, const float* __restrict__ cb,
                     float* __restrict__ qout, float* loss_out) {
    __shared__ float lred[8];

    const int h    = blockIdx.y;
    const int tok0 = blockIdx.x * TME;
    const int tid  = threadIdx.x;
    const float* xbase = x  + (size_t)tok0 * 1024 + h * DH;
    const float* cbase = cb + (size_t)h * NCODE * DH;

    float lsum = 0.f;
#pragma unroll 4
    for (int g = tid; g < TME * (DH / 4); g += 256) {
        int t  = g >> 6;
        int dq = g & 63;
        int k  = g_idx[h * N_TOK + tok0 + t];
        float4 c  = *(const float4*)(cbase + (size_t)k * DH + dq * 4);
        float4 xv = *(const float4*)(xbase + (size_t)t * 1024 + dq * 4);
        float dx0 = c.x - xv.x, dx1 = c.y - xv.y, dx2 = c.z - xv.z, dx3 = c.w - xv.w;
        lsum += dx0 * dx0 + dx1 * dx1 + dx2 * dx2 + dx3 * dx3;
        float* o = qout + (size_t)(tok0 + t) * 1024 + h * DH + dq * 4;  // 4B-aligned only
        o[0] = xv.x + dx0;
        o[1] = xv.y + dx1;
        o[2] = xv.z + dx2;
        o[3] = xv.w + dx3;
    }

    if (loss_out) {
#pragma unroll
        for (int off = 16; off > 0; off >>= 1)
            lsum += __shfl_down_sync(0xFFFFFFFFu, lsum, off);
        if ((tid & 31) == 0) lred[tid >> 5] = lsum;
        __syncthreads();
        if (tid == 0) {
            float s = 0.f;
#pragma unroll
            for (int w = 0; w < 8; w++) s += lred[w];
            atomicAdd(loss_out, s * (0.25f / (float)((size_t)N_TOK * 1024)));
        }
    }
}

extern "C" void kernel_launch(void* const* d_in, const int* in_sizes, int n_in,
                              void* d_out, int out_size) {
    const float* x  = (const float*)d_in[0];
    const float* cb = (const float*)d_in[1];
    float* out = (float*)d_out;

    const long long qelems = (long long)N_TOK * 1024;
    int has_loss = (out_size == (int)(qelems + 1)) ? 1 : 0;
    float* qout     = out + (has_loss ? 1 : 0);
    float* loss_out = has_loss ? out : (float*)0;

    static int smem_set = 0;
    const int DSMEM = (32768 + 2 * 4096) * 4;   // 160 KB
    if (!smem_set) {
        cudaFuncSetAttribute(vq_screen, cudaFuncAttributeMaxDynamicSharedMemorySize, DSMEM);
        smem_set = 1;
    }

    csq_kernel<<<(NHEAD * NCODE * 32 + 255) / 256, 256>>>(cb);
    xsq_kernel<<<(N_TOK * NHEAD * 32 + 255) / 256, 256>>>(x);
    if (has_loss) zero_loss_kernel<<<1, 1>>>(out);

    dim3 sgrid(N_TOK / 128, NHEAD);
    vq_screen<<<sgrid, 512, DSMEM>>>(x, cb);

    dim3 rgrid(N_TOK / 8, NHEAD);
    vq_rescore<<<rgrid, 256>>>(x, cb);

    dim3 egrid(N_TOK / TME, NHEAD);
    epilogue_kernel<<<egrid, 256>>>(x, cb, qout, loss_out);
}

// round 16
// speedup vs baseline: 2.9928x; 1.2076x over previous
#include <cuda_runtime.h>
#include <cstdint>

#define N_TOK 16384
#define NHEAD 4
#define NCODE 1024
#define DH    256
#define EPS   4.0f

// fp32 norm tables (FROZEN: bitwise-matched to XLA reduction emitter)
__device__ float g_csq[NHEAD * NCODE];
__device__ float g_xsq[N_TOK * NHEAD];
__device__ int   g_idx[NHEAD * N_TOK];
// screen results
__device__ int   g_cand[NHEAD * N_TOK * 16];
__device__ int   g_cnt [NHEAD * N_TOK];

__device__ __forceinline__ float to_tf32(float v) {
    float o;
    asm("cvt.rna.tf32.f32 %0, %1;" : "=f"(o) : "f"(v));
    return o;
}

// ---- FROZEN: XLA warp tree 16,8,4,2,1 ----
__device__ __forceinline__ float warp_tree(float v) {
#pragma unroll
    for (int off = 16; off > 0; off >>= 1)
        v = __fadd_rn(v, __shfl_down_sync(0xFFFFFFFFu, v, off));
    return v;
}

// ---- FROZEN: XLA row sum-of-squares ----
__device__ __forceinline__ float rowsq_xla(const float* __restrict__ row, int lane) {
    float W[4];
#pragma unroll
    for (int w = 0; w < 4; w++) {
        int t = lane + 32 * w;
        float2 v = *(const float2*)(row + 2 * t);
        float m0 = __fmul_rn(v.x, v.x);
        float m1 = __fmul_rn(v.y, v.y);
        float a  = __fadd_rn(m0, m1);
        W[w] = warp_tree(a);
    }
    return __fadd_rn(__fadd_rn(W[0], W[2]), __fadd_rn(W[1], W[3]));
}

__global__ void csq_kernel(const float* __restrict__ cb) {
    int warp = (blockIdx.x * blockDim.x + threadIdx.x) >> 5;
    int lane = threadIdx.x & 31;
    if (warp >= NHEAD * NCODE) return;
    float s = rowsq_xla(cb + (size_t)warp * DH, lane);
    if (lane == 0) g_csq[warp] = s;
}

__global__ void xsq_kernel(const float* __restrict__ x) {
    int warp = (blockIdx.x * blockDim.x + threadIdx.x) >> 5;
    int lane = threadIdx.x & 31;
    if (warp >= N_TOK * NHEAD) return;
    float s = rowsq_xla(x + (size_t)warp * DH, lane);
    if (lane == 0) g_xsq[warp] = s;
}

__global__ void zero_loss_kernel(float* p) { p[0] = 0.f; }

// ---------------- Phase A: tf32 tensor screen, 64x64 warp tiles ----------------
// 256 thr / 8 warps: warp = (wm in 0..1) x (wn in 0..3); warp tile 64 tok x 64 codes.
// XBuf: 128 tok x 256 d in a-fragment order (128 KB), staged once.
// CBuf: double-buffered b-fragment tiles for one 16-d half-chunk (2 x 16 KB).
__global__ __launch_bounds__(256, 1)
void vq_screen(const float* __restrict__ x, const float* __restrict__ cb) {
    extern __shared__ float dsm[];
    float* XBuf = dsm;                 // 32768 floats
    float* CBuf = dsm + 32768;         // 2 * 4096 floats

    __shared__ unsigned tokmin[128];
    __shared__ int cnt[128];
    __shared__ int cand[128][16];

    const int h    = blockIdx.y;
    const int tok0 = blockIdx.x * 128;
    const int tid  = threadIdx.x;
    const int warp = tid >> 5, lane = tid & 31;
    const int wm   = warp >> 2, wn = warp & 3;

    const float* xbase = x  + (size_t)tok0 * 1024 + h * DH;
    const float* cbase = cb + (size_t)h * NCODE * DH;

    if (tid < 128) { tokmin[tid] = 0x7F800000u; cnt[tid] = 0; }
    for (int i = tid; i < 128 * 16; i += 256) (&cand[0][0])[i] = 0;

    // ---- stage ALL of X into a-fragment layout (once; verified mapping) ----
    {
        int t  = tid >> 1;                 // token 0..127
        int r  = t & 15, tgs = t >> 4;
        const float* xrow = xbase + (size_t)t * 1024;
        int dbase = (tid & 1) * 128;
#pragma unroll
        for (int q = 0; q < 32; q++) {
            int d0 = dbase + q * 4;
            float4 v = *(const float4*)(xrow + d0);
            int kc8 = d0 >> 3;
            int c8  = d0 & 7;              // 0 or 4
            int slot = (r >> 3) + ((c8 >> 2) << 1);
            float* bp = XBuf + (size_t)((tgs * 32 + kc8) * 32) * 4;
            int lb = (r & 7) * 4;
            bp[(lb + 0) * 4 + slot] = to_tf32(v.x);
            bp[(lb + 1) * 4 + slot] = to_tf32(v.y);
            bp[(lb + 2) * 4 + slot] = to_tf32(v.z);
            bp[(lb + 3) * 4 + slot] = to_tf32(v.w);
        }
    }

    // per-thread C staging coords: i-th fragment F = tid + i*256
    // F -> tile tl = F>>5 (p = tl>>4, wnS = (tl>>2)&3, npS = tl&3), lane l = F&31
    int coff0[4];   // n0*DH + p*8 + (l&3)
#pragma unroll
    for (int i = 0; i < 4; i++) {
        int F  = tid + i * 256;
        int tl = F >> 5, l = F & 31;
        int p   = tl >> 4;
        int wnS = (tl >> 2) & 3;
        int npS = tl & 3;
        int n0  = wnS * 64 + npS * 16 + (l >> 2);
        coff0[i] = n0 * DH + p * 8 + (l & 3);
    }

    // xsq for my 8 token rows
    float xsq0[4], xsq1[4];
#pragma unroll
    for (int mt = 0; mt < 4; mt++) {
        int t0 = wm * 64 + mt * 16 + (lane >> 2);
        xsq0[mt] = g_xsq[(size_t)(tok0 + t0) * NHEAD + h];
        xsq1[mt] = g_xsq[(size_t)(tok0 + t0 + 8) * NHEAD + h];
    }

    float acc[4][8][4];   // [mt][nt = np*2+tile][comp]
#pragma unroll
    for (int mt = 0; mt < 4; mt++)
#pragma unroll
        for (int nt = 0; nt < 8; nt++)
#pragma unroll
            for (int c = 0; c < 4; c++) acc[mt][nt][c] = 0.f;

    // prologue: LDG fragments for idx 0 (cbi=0, hc=0)
    float4 cr[4];
#pragma unroll
    for (int i = 0; i < 4; i++) {
        const float* p0 = cbase + coff0[i];
        cr[i].x = p0[0];
        cr[i].y = p0[4];
        cr[i].z = p0[2048];        // n0+8 row
        cr[i].w = p0[2048 + 4];
    }

    for (int idx = 0; idx < 64; idx++) {
        const int cbi = idx >> 4;
        const int hc  = idx & 15;
        const int b   = idx & 1;

        // STS: one conflict-free STS.128 per fragment
        {
            float4* cp = (float4*)(CBuf + b * 4096);
#pragma unroll
            for (int i = 0; i < 4; i++) {
                float4 w;
                w.x = to_tf32(cr[i].x); w.y = to_tf32(cr[i].y);
                w.z = to_tf32(cr[i].z); w.w = to_tf32(cr[i].w);
                cp[tid + i * 256] = w;
            }
        }
        // issue next LDGs early (overlap with barrier + MMA)
        if (idx < 63) {
            int idn = idx + 1;
            const float* base = cbase + (size_t)(idn >> 4) * 256 * DH + (idn & 15) * 16;
#pragma unroll
            for (int i = 0; i < 4; i++) {
                const float* p0 = base + coff0[i];
                cr[i].x = p0[0];
                cr[i].y = p0[4];
                cr[i].z = p0[2048];
                cr[i].w = p0[2048 + 4];
            }
        }
        __syncthreads();

        // MMA: 2 k8-steps, 4 a-frags x 4 b-float4s -> 32 HMMA
#pragma unroll
        for (int p = 0; p < 2; p++) {
            float4 av[4];
#pragma unroll
            for (int mt = 0; mt < 4; mt++)
                av[mt] = ((const float4*)XBuf)[((wm * 4 + mt) * 32 + hc * 2 + p) * 32 + lane];
#pragma unroll
            for (int np = 0; np < 4; np++) {
                float4 bv = ((const float4*)(CBuf + b * 4096))[(p * 16 + wn * 4 + np) * 32 + lane];
                uint32_t b0 = __float_as_uint(bv.x), b1 = __float_as_uint(bv.y);
                uint32_t b2 = __float_as_uint(bv.z), b3 = __float_as_uint(bv.w);
#pragma unroll
                for (int mt = 0; mt < 4; mt++) {
                    uint32_t a0 = __float_as_uint(av[mt].x), a1 = __float_as_uint(av[mt].y);
                    uint32_t a2 = __float_as_uint(av[mt].z), a3 = __float_as_uint(av[mt].w);
                    asm volatile(
                        "mma.sync.aligned.m16n8k8.row.col.f32.tf32.tf32.f32 "
                        "{%0,%1,%2,%3}, {%4,%5,%6,%7}, {%8,%9}, {%0,%1,%2,%3};"
                        : "+f"(acc[mt][np * 2][0]), "+f"(acc[mt][np * 2][1]),
                          "+f"(acc[mt][np * 2][2]), "+f"(acc[mt][np * 2][3])
                        : "r"(a0), "r"(a1), "r"(a2), "r"(a3), "r"(b0), "r"(b1));
                    asm volatile(
                        "mma.sync.aligned.m16n8k8.row.col.f32.tf32.tf32.f32 "
                        "{%0,%1,%2,%3}, {%4,%5,%6,%7}, {%8,%9}, {%0,%1,%2,%3};"
                        : "+f"(acc[mt][np * 2 + 1][0]), "+f"(acc[mt][np * 2 + 1][1]),
                          "+f"(acc[mt][np * 2 + 1][2]), "+f"(acc[mt][np * 2 + 1][3])
                        : "r"(a0), "r"(a1), "r"(a2), "r"(a3), "r"(b2), "r"(b3));
                }
            }
        }

        if (hc == 15) {
            // sweep 1: per-token thread-local min -> smem atomicMin
            float m0[4], m1[4];
#pragma unroll
            for (int mt = 0; mt < 4; mt++) { m0[mt] = 3.4e38f; m1[mt] = 3.4e38f; }
#pragma unroll
            for (int nt = 0; nt < 8; nt++)
#pragma unroll
                for (int c = 0; c < 2; c++) {
                    int k = cbi * 256 + wn * 64 + nt * 8 + 2 * (lane & 3) + c;
                    float csqv = g_csq[h * NCODE + k];
#pragma unroll
                    for (int mt = 0; mt < 4; mt++) {
                        m0[mt] = fminf(m0[mt], xsq0[mt] + csqv - 2.f * acc[mt][nt][c]);
                        m1[mt] = fminf(m1[mt], xsq1[mt] + csqv - 2.f * acc[mt][nt][c + 2]);
                    }
                }
#pragma unroll
            for (int mt = 0; mt < 4; mt++) {
                int t0 = wm * 64 + mt * 16 + (lane >> 2);
                atomicMin(&tokmin[t0], __float_as_uint(m0[mt]));
                atomicMin(&tokmin[t0 + 8], __float_as_uint(m1[mt]));
            }
            __syncthreads();

            // sweep 2: collect candidates within EPS of running min
            float th0[4], th1[4];
#pragma unroll
            for (int mt = 0; mt < 4; mt++) {
                int t0 = wm * 64 + mt * 16 + (lane >> 2);
                th0[mt] = __uint_as_float(tokmin[t0]) + EPS;
                th1[mt] = __uint_as_float(tokmin[t0 + 8]) + EPS;
            }
#pragma unroll
            for (int nt = 0; nt < 8; nt++)
#pragma unroll
                for (int c = 0; c < 2; c++) {
                    int k = cbi * 256 + wn * 64 + nt * 8 + 2 * (lane & 3) + c;
                    float csqv = g_csq[h * NCODE + k];
#pragma unroll
                    for (int mt = 0; mt < 4; mt++) {
                        int t0 = wm * 64 + mt * 16 + (lane >> 2);
                        float d0 = xsq0[mt] + csqv - 2.f * acc[mt][nt][c];
                        float d1 = xsq1[mt] + csqv - 2.f * acc[mt][nt][c + 2];
                        if (d0 <= th0[mt]) {
                            int pos = atomicAdd(&cnt[t0], 1);
                            if (pos < 16) cand[t0][pos] = k;
                        }
                        if (d1 <= th1[mt]) {
                            int pos = atomicAdd(&cnt[t0 + 8], 1);
                            if (pos < 16) cand[t0 + 8][pos] = k;
                        }
                    }
                }
            __syncthreads();

#pragma unroll
            for (int mt = 0; mt < 4; mt++)
#pragma unroll
                for (int nt = 0; nt < 8; nt++)
#pragma unroll
                    for (int c = 0; c < 4; c++) acc[mt][nt][c] = 0.f;
        }
    }

    if (tid < 128) {
        int tokg = h * N_TOK + tok0 + tid;
        g_cnt[tokg] = cnt[tid];
#pragma unroll
        for (int j = 0; j < 16; j++) g_cand[(size_t)tokg * 16 + j] = cand[tid][j];
    }
}

// ---------------- Phase B: exact rescore (FROZEN serial chain per candidate) ----------------
__global__ __launch_bounds__(256)
void vq_rescore(const float* __restrict__ x, const float* __restrict__ cb) {
    const int h    = blockIdx.y;
    const int tok  = blockIdx.x * 8 + (threadIdx.x >> 5);
    const int lane = threadIdx.x & 31;

    const int   tokg = h * N_TOK + tok;
    const int   n    = g_cnt[tokg];
    const float xsqv = g_xsq[(size_t)tok * NHEAD + h];
    const float* xrow = x + ((size_t)tok * NHEAD + h) * DH;

    float bv = 3.4e38f;
    int   bi = 0x7FFFFFFF;

    auto score = [&](int k) {
        const float* crow = cb + ((size_t)h * NCODE + k) * DH;
        float a = 0.f;
#pragma unroll 8
        for (int d4 = 0; d4 < DH / 4; d4++) {
            float4 xv = *(const float4*)(xrow + d4 * 4);
            float4 cv = *(const float4*)(crow + d4 * 4);
            a = fmaf(xv.x, cv.x, a);
            a = fmaf(xv.y, cv.y, a);
            a = fmaf(xv.z, cv.z, a);
            a = fmaf(xv.w, cv.w, a);
        }
        float t1   = __fadd_rn(xsqv, g_csq[h * NCODE + k]);
        float dist = __fsub_rn(t1, __fmul_rn(2.f, a));
        if (dist < bv || (dist == bv && k < bi)) { bv = dist; bi = k; }
    };

    if (n <= 16) {
        if (lane < n) score(g_cand[(size_t)tokg * 16 + lane]);
    } else {
        for (int k = lane; k < NCODE; k += 32) score(k);
    }

#pragma unroll
    for (int off = 16; off > 0; off >>= 1) {
        float vo = __shfl_down_sync(0xFFFFFFFFu, bv, off);
        int   io = __shfl_down_sync(0xFFFFFFFFu, bi, off);
        if (vo < bv || (vo == bv && io < bi)) { bv = vo; bi = io; }
    }
    if (lane == 0) g_idx[tokg] = bi;
}

// ---------------- epilogue: gather + straight-through + loss ----------------
#define TME 64
__global__ __launch_bounds__(256)
void epilogue_kernel(const float* __restrict__ x, const float* __restrict__ cb,
                     float* __restrict__ qout, float* loss_out) {
    __shared__ float lred[8];

    const int h    = blockIdx.y;
    const int tok0 = blockIdx.x * TME;
    const int tid  = threadIdx.x;
    const float* xbase = x  + (size_t)tok0 * 1024 + h * DH;
    const float* cbase = cb + (size_t)h * NCODE * DH;

    float lsum = 0.f;
#pragma unroll 4
    for (int g = tid; g < TME * (DH / 4); g += 256) {
        int t  = g >> 6;
        int dq = g & 63;
        int k  = g_idx[h * N_TOK + tok0 + t];
        float4 c  = *(const float4*)(cbase + (size_t)k * DH + dq * 4);
        float4 xv = *(const float4*)(xbase + (size_t)t * 1024 + dq * 4);
        float dx0 = c.x - xv.x, dx1 = c.y - xv.y, dx2 = c.z - xv.z, dx3 = c.w - xv.w;
        lsum += dx0 * dx0 + dx1 * dx1 + dx2 * dx2 + dx3 * dx3;
        float* o = qout + (size_t)(tok0 + t) * 1024 + h * DH + dq * 4;  // 4B-aligned only
        o[0] = xv.x + dx0;
        o[1] = xv.y + dx1;
        o[2] = xv.z + dx2;
        o[3] = xv.w + dx3;
    }

    if (loss_out) {
#pragma unroll
        for (int off = 16; off > 0; off >>= 1)
            lsum += __shfl_down_sync(0xFFFFFFFFu, lsum, off);
        if ((tid & 31) == 0) lred[tid >> 5] = lsum;
        __syncthreads();
        if (tid == 0) {
            float s = 0.f;
#pragma unroll
            for (int w = 0; w < 8; w++) s += lred[w];
            atomicAdd(loss_out, s * (0.25f / (float)((size_t)N_TOK * 1024)));
        }
    }
}

extern "C" void kernel_launch(void* const* d_in, const int* in_sizes, int n_in,
                              void* d_out, int out_size) {
    const float* x  = (const float*)d_in[0];
    const float* cb = (const float*)d_in[1];
    float* out = (float*)d_out;

    const long long qelems = (long long)N_TOK * 1024;
    int has_loss = (out_size == (int)(qelems + 1)) ? 1 : 0;
    float* qout     = out + (has_loss ? 1 : 0);
    float* loss_out = has_loss ? out : (float*)0;

    static int smem_set = 0;
    const int DSMEM = (32768 + 2 * 4096) * 4;   // 160 KB
    if (!smem_set) {
        cudaFuncSetAttribute(vq_screen, cudaFuncAttributeMaxDynamicSharedMemorySize, DSMEM);
        smem_set = 1;
    }

    csq_kernel<<<(NHEAD * NCODE * 32 + 255) / 256, 256>>>(cb);
    xsq_kernel<<<(N_TOK * NHEAD * 32 + 255) / 256, 256>>>(x);
    if (has_loss) zero_loss_kernel<<<1, 1>>>(out);

    dim3 sgrid(N_TOK / 128, NHEAD);
    vq_screen<<<sgrid, 256, DSMEM>>>(x, cb);

    dim3 rgrid(N_TOK / 8, NHEAD);
    vq_rescore<<<rgrid, 256>>>(x, cb);

    dim3 egrid(N_TOK / TME, NHEAD);
    epilogue_kernel<<<egrid, 256>>>(x, cb, qout, loss_out);
}